// round 4
// baseline (speedup 1.0000x reference)
#include <cuda_runtime.h>
#include <math.h>

// LatentRNN: B=2048, T=512, P=8, L=64, H=180
// 128 persistent CTAs x 16 batch rows. All state in SMEM. SMEM-staged,
// double-buffered weight tiles; plain fp32 FFMA (f32x2 removed after R3).

#define B_    2048
#define T_    512
#define P_    8
#define L_    64
#define H_    180
#define IN_K  72
#define CAT_K 244
#define BT    16
#define NTHR  384
#define KT    36
#define WS    37

struct __align__(16) Smem {
    float inT[IN_K][BT];       // [phys_t ; cur] transposed
    float xT [H_][BT];         // gelu(in @ W_in^T)
    float hT [2][H_][BT];      // hidden state, double buffered
    float giT[3*H_][BT];       // x @ W_ih^T   (alias: catT rows 0..243)
    float ghT[3*H_][BT];       // h @ W_hh^T   (alias: oT rows 0..179)
    float cur[BT][L_];         // current latents
    float Wt [2][360*WS];      // double-buffered staged weight tiles
};

__device__ __forceinline__ float gelu_f(float v) {
    return 0.5f * v * (1.0f + erff(v * 0.70710678118654752440f));
}
__device__ __forceinline__ float sigmoid_f(float v) {
    return 1.0f / (1.0f + expf(-v));
}

// Stage a K-tile (F4 float4-chunks per row) of one [NCOLS x ldw] matrix.
// Interleaved mapping -> coalesced LDG.128; scalar STS (WS=37 odd stride).
template<int NCOLS, int F4>
__device__ __forceinline__ void stage(float* __restrict__ dst,
                                      const float* __restrict__ W, int ldw,
                                      int k0, int tid) {
    for (int i = tid; i < NCOLS * F4; i += NTHR) {
        int r = i / F4, c = i - r * F4;
        float4 v = *(const float4*)(W + r * ldw + k0 + c * 4);
        float* d = dst + r * WS + c * 4;
        d[0] = v.x; d[1] = v.y; d[2] = v.z; d[3] = v.w;
    }
}

// Core: NC cols x 4 rows, one K-tile. act reads warp-quasi-uniform LDS.128;
// weight reads scalar LDS, conflict-free (odd WS).
template<int NC>
__device__ __forceinline__ void tile_fma(const float* __restrict__ wr,
                                         const float (*__restrict__ act)[BT],
                                         int k0, int klen, int rowoff,
                                         float* __restrict__ acc) {
#pragma unroll 4
    for (int k = 0; k < klen; k++) {
        float4 a = *(const float4*)&act[k0 + k][rowoff];
#pragma unroll
        for (int c = 0; c < NC; c++) {
            float w = wr[c * WS + k];
            acc[4*c+0] += a.x * w; acc[4*c+1] += a.y * w;
            acc[4*c+2] += a.z * w; acc[4*c+3] += a.w * w;
        }
    }
}

// Generic staged GEMM phase: outT[j][r] = (gelu?)(act^T W^T + b).
template<int NCOLS, int NC, int K, bool GELU>
__device__ void gemm_phase(Smem* __restrict__ s, const float* __restrict__ W,
                           const float* __restrict__ bias,
                           const float (*__restrict__ act)[BT],
                           float (*__restrict__ outT)[BT], int tid) {
    constexpr int NT     = (K + KT - 1) / KT;
    constexpr int KLAST  = K - (NT - 1) * KT;
    constexpr int F4LAST = KLAST / 4;
    constexpr int NTASK  = (NCOLS / NC) * 4;
    const int cg = tid >> 2, q = tid & 3;
    const int col0 = cg * NC, rowoff = q * 4;
    const bool on = tid < NTASK;
    float acc[4 * NC];
#pragma unroll
    for (int i = 0; i < 4 * NC; i++) acc[i] = 0.f;

    stage<NCOLS, 9>(s->Wt[0], W, K, 0, tid);
    __syncthreads();
#pragma unroll
    for (int kt = 0; kt < NT; kt++) {
        if (kt + 1 < NT) {
            if (kt + 1 == NT - 1)
                stage<NCOLS, F4LAST>(s->Wt[(kt + 1) & 1], W, K, (kt + 1) * KT, tid);
            else
                stage<NCOLS, 9>(s->Wt[(kt + 1) & 1], W, K, (kt + 1) * KT, tid);
        }
        if (on) {
            const int klen = (kt == NT - 1) ? KLAST : KT;
            tile_fma<NC>(&s->Wt[kt & 1][col0 * WS], act, kt * KT, klen, rowoff, acc);
        }
        __syncthreads();
    }
    if (on) {
#pragma unroll
        for (int c = 0; c < NC; c++) {
            float bb = bias[col0 + c];
            float4 f;
            f.x = acc[4*c+0] + bb; f.y = acc[4*c+1] + bb;
            f.z = acc[4*c+2] + bb; f.w = acc[4*c+3] + bb;
            if (GELU) { f.x = gelu_f(f.x); f.y = gelu_f(f.y);
                        f.z = gelu_f(f.z); f.w = gelu_f(f.w); }
            *(float4*)&outT[col0 + c][rowoff] = f;
        }
    }
}

// Phase C staging: virtual 1080-col matrix [W_ih ; W_hh], block p of 360 cols.
__device__ __forceinline__ void stageC(float* __restrict__ dst,
                                       const float* __restrict__ W_ih,
                                       const float* __restrict__ W_hh,
                                       int p, int k0, int tid) {
    for (int i = tid; i < 360 * 9; i += NTHR) {
        int r = i / 9, c = i - r * 9;
        int g = p * 360 + r;
        const float* src = (g < 540) ? (W_ih + g * H_ + k0 + c * 4)
                                     : (W_hh + (g - 540) * H_ + k0 + c * 4);
        float4 v = *(const float4*)src;
        float* d = dst + r * WS + c * 4;
        d[0] = v.x; d[1] = v.y; d[2] = v.z; d[3] = v.w;
    }
}

// Phase C: gi = x @ W_ih^T + b_ih ; gh = h @ W_hh^T + b_hh (1080 cols, 3 passes).
__device__ void phaseC(Smem* __restrict__ s, const float* __restrict__ W_ih,
                       const float* __restrict__ W_hh,
                       const float* __restrict__ b_ih,
                       const float* __restrict__ b_hh, int cb, int tid) {
    const int cg = tid >> 2, q = tid & 3, rowoff = q * 4;
    const bool on = tid < 360;
    for (int p = 0; p < 3; p++) {
        const int g0 = p * 360 + cg * 4;   // 4-col group never straddles 540
        const float (*act)[BT] = (g0 < 540) ? (const float (*)[BT])s->xT
                                            : (const float (*)[BT])s->hT[cb];
        float acc[16];
#pragma unroll
        for (int i = 0; i < 16; i++) acc[i] = 0.f;

        stageC(s->Wt[0], W_ih, W_hh, p, 0, tid);
        __syncthreads();
#pragma unroll
        for (int kt = 0; kt < 5; kt++) {
            if (kt < 4) stageC(s->Wt[(kt + 1) & 1], W_ih, W_hh, p, (kt + 1) * KT, tid);
            if (on)
                tile_fma<4>(&s->Wt[kt & 1][(cg * 4) * WS], act, kt * KT, KT, rowoff, acc);
            __syncthreads();
        }
        if (on) {
#pragma unroll
            for (int c = 0; c < 4; c++) {
                int g = g0 + c;
                float bb; float* orow;
                if (g < 540) { bb = b_ih[g];       orow = s->giT[g]; }
                else         { bb = b_hh[g - 540]; orow = s->ghT[g - 540]; }
                float4 f;
                f.x = acc[4*c+0] + bb; f.y = acc[4*c+1] + bb;
                f.z = acc[4*c+2] + bb; f.w = acc[4*c+3] + bb;
                *(float4*)&orow[rowoff] = f;
            }
        }
    }
}

// Phase E: delta = oT @ W_o2^T + b_o2 ; cur = clip(cur + delta); store out.
__device__ void phaseE(Smem* __restrict__ s, const float* __restrict__ W_o2,
                       const float* __restrict__ b_o2,
                       float* __restrict__ out, int b0, int t, int tid) {
    const int j = tid & 63, q = tid >> 6;   // active: tid < 256 (q < 4)
    const bool on = tid < 256;
    const int rowoff = q * 4;
    float acc[4] = {0.f, 0.f, 0.f, 0.f};

    stage<L_, 9>(s->Wt[0], W_o2, H_, 0, tid);
    __syncthreads();
#pragma unroll
    for (int kt = 0; kt < 5; kt++) {
        if (kt < 4) stage<L_, 9>(s->Wt[(kt + 1) & 1], W_o2, H_, (kt + 1) * KT, tid);
        if (on)
            tile_fma<1>(&s->Wt[kt & 1][j * WS],
                        (const float (*)[BT])s->ghT, kt * KT, KT, rowoff, acc); // oT alias
        __syncthreads();
    }
    if (on) {
        float bb = b_o2[j];
#pragma unroll
        for (int i = 0; i < 4; i++) {
            int r = rowoff + i;
            float c = fminf(fmaxf(s->cur[r][j] + acc[i] + bb, 0.f), 1.f);
            s->cur[r][j] = c;
            out[((size_t)(b0 + r) * T_ + t) * L_ + j] = c;
        }
    }
}

// One-time h0 projection (plain fp32 col-GEMM).
__device__ __forceinline__ void colgemm(const float* __restrict__ w, int K,
                                        const float (*__restrict__ in)[BT],
                                        float* __restrict__ acc) {
#pragma unroll 4
    for (int k = 0; k < K; k += 4) {
        float4 wv = *(const float4*)(w + k);
        float wa[4] = {wv.x, wv.y, wv.z, wv.w};
#pragma unroll
        for (int kk = 0; kk < 4; kk++) {
            const float4* xr = (const float4*)(in[k + kk]);
            float4 a = xr[0], b = xr[1], c = xr[2], d = xr[3];
            float w0 = wa[kk];
            acc[0]  += a.x * w0; acc[1]  += a.y * w0; acc[2]  += a.z * w0; acc[3]  += a.w * w0;
            acc[4]  += b.x * w0; acc[5]  += b.y * w0; acc[6]  += b.z * w0; acc[7]  += b.w * w0;
            acc[8]  += c.x * w0; acc[9]  += c.y * w0; acc[10] += c.z * w0; acc[11] += c.w * w0;
            acc[12] += d.x * w0; acc[13] += d.y * w0; acc[14] += d.z * w0; acc[15] += d.w * w0;
        }
    }
}

__global__ __launch_bounds__(NTHR, 1)
void latent_rnn_kernel(const float* __restrict__ phys,
                       const float* __restrict__ latents,
                       const float* __restrict__ W_in, const float* __restrict__ b_in,
                       const float* __restrict__ W_hp, const float* __restrict__ b_hp,
                       const float* __restrict__ W_ih, const float* __restrict__ b_ih,
                       const float* __restrict__ W_hh, const float* __restrict__ b_hh,
                       const float* __restrict__ W_o1, const float* __restrict__ b_o1,
                       const float* __restrict__ W_o2, const float* __restrict__ b_o2,
                       float* __restrict__ out)
{
    extern __shared__ char smem_raw[];
    Smem* s = reinterpret_cast<Smem*>(smem_raw);
    const int tid = threadIdx.x;
    const int b0  = blockIdx.x * BT;

    // init: cur = latents; stage latents^T for h0 GEMM
    for (int i = tid; i < BT * L_; i += NTHR) {
        int r = i >> 6, l = i & 63;
        float v = latents[(b0 + r) * L_ + l];
        s->cur[r][l] = v;
        s->inT[l][r] = v;
    }
    __syncthreads();

    // h0 = latents @ W_hp^T + b_hp
    for (int j = tid; j < H_; j += NTHR) {
        float acc[BT];
#pragma unroll
        for (int r = 0; r < BT; r++) acc[r] = 0.f;
        colgemm(W_hp + j * L_, L_, (const float (*)[BT])s->inT, acc);
        float bb = b_hp[j];
#pragma unroll
        for (int r = 0; r < BT; r++) s->hT[0][j][r] = acc[r] + bb;
    }

    for (int t = 0; t < T_; t++) {
        const int cb = t & 1, nb = cb ^ 1;
        __syncthreads();   // prev-E cur writes (and h0) -> A

        // A: inT = [phys_t ; cur] transposed
        for (int i = tid; i < BT * IN_K; i += NTHR) {
            int r = i / IN_K, k = i - r * IN_K;
            s->inT[k][r] = (k < P_) ? phys[((size_t)(b0 + r) * T_ + t) * P_ + k]
                                    : s->cur[r][k - P_];
        }
        // B: xT = gelu(inT @ W_in^T + b_in)  (A-writes ordered by B's first sync)
        gemm_phase<H_, 2, IN_K, true>(s, W_in, b_in,
                                      (const float (*)[BT])s->inT, s->xT, tid);
        // C: gi/gh GEMMs
        phaseC(s, W_ih, W_hh, b_ih, b_hh, cb, tid);

        // gates: h_new; catT[j] (alias giT) = h_new
        for (int i = tid; i < H_ * BT; i += NTHR) {
            int j = i >> 4, r = i & 15;
            float rg = sigmoid_f(s->giT[j][r] + s->ghT[j][r]);
            float zg = sigmoid_f(s->giT[j + H_][r] + s->ghT[j + H_][r]);
            float ng = tanhf(s->giT[j + 2 * H_][r] + rg * s->ghT[j + 2 * H_][r]);
            float hn = (1.f - zg) * ng + zg * s->hT[cb][j][r];
            s->hT[nb][j][r] = hn;
            s->giT[j][r] = hn;     // element owned by this thread
        }
        __syncthreads();           // z-rows consumed before cur-copy aliases them

        // catT[H..H+L) = cur
        for (int i = tid; i < L_ * BT; i += NTHR) {
            int l = i >> 4, r = i & 15;
            s->giT[H_ + l][r] = s->cur[r][l];
        }
        // D: oT (alias ghT) = gelu(catT @ W_o1^T + b_o1)
        gemm_phase<H_, 2, CAT_K, true>(s, W_o1, b_o1,
                                       (const float (*)[BT])s->giT, s->ghT, tid);
        // E: cur update + output store
        phaseE(s, W_o2, b_o2, out, b0, t, tid);
    }
}

extern "C" void kernel_launch(void* const* d_in, const int* in_sizes, int n_in,
                              void* d_out, int out_size)
{
    const float* phys    = (const float*)d_in[0];
    const float* latents = (const float*)d_in[1];
    const float* W_in    = (const float*)d_in[2];
    const float* b_in    = (const float*)d_in[3];
    const float* W_hp    = (const float*)d_in[4];
    const float* b_hp    = (const float*)d_in[5];
    const float* W_ih    = (const float*)d_in[6];
    const float* b_ih    = (const float*)d_in[7];
    const float* W_hh    = (const float*)d_in[8];
    const float* b_hh    = (const float*)d_in[9];
    const float* W_o1    = (const float*)d_in[10];
    const float* b_o1    = (const float*)d_in[11];
    const float* W_o2    = (const float*)d_in[12];
    const float* b_o2    = (const float*)d_in[13];
    float* out = (float*)d_out;

    static bool attr_set = false;
    if (!attr_set) {
        cudaFuncSetAttribute(latent_rnn_kernel,
                             cudaFuncAttributeMaxDynamicSharedMemorySize,
                             (int)sizeof(Smem));
        attr_set = true;
    }

    latent_rnn_kernel<<<B_ / BT, NTHR, sizeof(Smem)>>>(
        phys, latents, W_in, b_in, W_hp, b_hp, W_ih, b_ih, W_hh, b_hh,
        W_o1, b_o1, W_o2, b_o2, out);
}